// round 13
// baseline (speedup 1.0000x reference)
#include <cuda_runtime.h>
#include <math.h>

#define V_TOTAL 50000
#define E_DIM   512
#define T_TOTAL 4096
#define BATCH_ELEMS 2097152    // 8*512*512
#define EMB_ELEMS   25600000   // 50000*512

#define TM 128
#define TN 128
#define BK 32
#define S_STRIDE 132   // padded shared stride (floats)

// Scratch (allocation-free rule: __device__ globals)
__device__ float g_inv_norm[50048];
__device__ unsigned long long g_best[T_TOTAL];

// ordered-float + inverted-index key: bigger value wins; ties -> smaller index wins
__device__ __forceinline__ unsigned long long enc_key(float f, unsigned v) {
    unsigned u = __float_as_uint(f);
    u = (u & 0x80000000u) ? ~u : (u | 0x80000000u);
    return ((unsigned long long)u << 32) | (unsigned long long)(0xFFFFFFFFu - v);
}

// ---------- kernel: reset best keys ----------
__global__ void k_init() {
    int i = blockIdx.x * blockDim.x + threadIdx.x;
    if (i < T_TOTAL) g_best[i] = 0ULL;
}

// ---------- kernel: per-row 1/||emb_v|| (one warp per row) ----------
__global__ void k_norm(const float* __restrict__ emb) {
    int warp = (blockIdx.x * blockDim.x + threadIdx.x) >> 5;
    int lane = threadIdx.x & 31;
    if (warp >= V_TOTAL) return;
    const float4* row = (const float4*)(emb + (size_t)warp * E_DIM);
    float s = 0.f;
#pragma unroll
    for (int i = 0; i < 4; i++) {
        float4 v = row[lane + i * 32];
        s += v.x * v.x + v.y * v.y + v.z * v.z + v.w * v.w;
    }
#pragma unroll
    for (int o = 16; o; o >>= 1) s += __shfl_xor_sync(0xffffffffu, s, o);
    // Guard: zero norm -> inv 0 (instead of inf), keeps scores finite.
    if (lane == 0) g_inv_norm[warp] = (s > 0.f) ? (1.0f / sqrtf(s)) : 0.f;
}

// ---------- fused GEMM + argmax ----------
// C[t][v] = sum_k batch[t][k] * emb[v][k]; score = C * inv_norm[v]; argmax over v.
__global__ __launch_bounds__(256) void k_gemm(const float* __restrict__ A,
                                              const float* __restrict__ B) {
    __shared__ float As[BK][S_STRIDE];
    __shared__ float Bs[BK][S_STRIDE];
    __shared__ unsigned long long rowBest[TM];

    const int tid = threadIdx.x;
    const int tx = tid & 15;        // column group
    const int ty = tid >> 4;        // row group
    const int t0 = blockIdx.y * TM; // token tile base (4096/128 = 32, exact)
    const int v0 = blockIdx.x * TN; // vocab tile base (391 tiles, last partial)

    float acc[8][8];
#pragma unroll
    for (int i = 0; i < 8; i++)
#pragma unroll
        for (int j = 0; j < 8; j++) acc[i][j] = 0.f;

    float4 ar[4], br[4];

    // initial prefetch (kt = 0)
#pragma unroll
    for (int i = 0; i < 4; i++) {
        int q = tid + i * 256;
        int row = q >> 3, kq = q & 7;
        ar[i] = *(const float4*)(A + (size_t)(t0 + row) * E_DIM + kq * 4);
        int v = v0 + row;
        br[i] = (v < V_TOTAL)
                    ? *(const float4*)(B + (size_t)v * E_DIM + kq * 4)
                    : make_float4(0.f, 0.f, 0.f, 0.f);
    }

    for (int kt = 0; kt < E_DIM / BK; kt++) {
        __syncthreads();
        // store prefetched tile (transposed: As[k][row])
#pragma unroll
        for (int i = 0; i < 4; i++) {
            int q = tid + i * 256;
            int row = q >> 3, kq = q & 7;
            As[kq * 4 + 0][row] = ar[i].x;
            As[kq * 4 + 1][row] = ar[i].y;
            As[kq * 4 + 2][row] = ar[i].z;
            As[kq * 4 + 3][row] = ar[i].w;
            Bs[kq * 4 + 0][row] = br[i].x;
            Bs[kq * 4 + 1][row] = br[i].y;
            Bs[kq * 4 + 2][row] = br[i].z;
            Bs[kq * 4 + 3][row] = br[i].w;
        }
        __syncthreads();

        // prefetch next tile
        if (kt + 1 < E_DIM / BK) {
            int k0 = (kt + 1) * BK;
#pragma unroll
            for (int i = 0; i < 4; i++) {
                int q = tid + i * 256;
                int row = q >> 3, kq = q & 7;
                ar[i] = *(const float4*)(A + (size_t)(t0 + row) * E_DIM + k0 + kq * 4);
                int v = v0 + row;
                br[i] = (v < V_TOTAL)
                            ? *(const float4*)(B + (size_t)v * E_DIM + k0 + kq * 4)
                            : make_float4(0.f, 0.f, 0.f, 0.f);
            }
        }

        // compute: rows {4ty..4ty+3, 64+4ty..}, cols {4tx..4tx+3, 64+4tx..}
#pragma unroll
        for (int kk = 0; kk < BK; kk++) {
            float4 a0 = *(const float4*)&As[kk][4 * ty];
            float4 a1 = *(const float4*)&As[kk][64 + 4 * ty];
            float4 b0 = *(const float4*)&Bs[kk][4 * tx];
            float4 b1 = *(const float4*)&Bs[kk][64 + 4 * tx];
            float a[8] = {a0.x, a0.y, a0.z, a0.w, a1.x, a1.y, a1.z, a1.w};
            float b[8] = {b0.x, b0.y, b0.z, b0.w, b1.x, b1.y, b1.z, b1.w};
#pragma unroll
            for (int i = 0; i < 8; i++)
#pragma unroll
                for (int j = 0; j < 8; j++)
                    acc[i][j] = fmaf(a[i], b[j], acc[i][j]);
        }
    }

    // ---- epilogue: scale by inv_norm, per-row argmax ----
    float invc[8];
    int colv[8];
#pragma unroll
    for (int j = 0; j < 8; j++) {
        int c = (j < 4) ? (4 * tx + j) : (64 + 4 * tx + (j - 4));
        int v = v0 + c;
        colv[j] = v;
        invc[j] = (v < V_TOTAL) ? g_inv_norm[v] : 0.f;
    }

    unsigned long long key[8];
#pragma unroll
    for (int i = 0; i < 8; i++) {
        unsigned long long best = 0ULL;
#pragma unroll
        for (int j = 0; j < 8; j++) {
            if (colv[j] < V_TOTAL) {
                float score = acc[i][j] * invc[j];
                if (score == score) {  // NaN-proof: skip non-comparable scores
                    unsigned long long k = enc_key(score, (unsigned)colv[j]);
                    if (k > best) best = k;
                }
            }
        }
        key[i] = best;
    }

    __syncthreads();
    if (tid < TM) rowBest[tid] = 0ULL;
    __syncthreads();
#pragma unroll
    for (int i = 0; i < 8; i++) {
        int r = (i < 4) ? (4 * ty + i) : (64 + 4 * ty + (i - 4));
        if (key[i]) atomicMax(&rowBest[r], key[i]);
    }
    __syncthreads();
    if (tid < TM) {
        unsigned long long k = rowBest[tid];
        if (k) atomicMax(&g_best[t0 + tid], k);
    }
}

// ---------- decode: write winning index as FLOAT32 ----------
// Hypothesis under test: harness __output__ dtype is float32 (dataset stores
// all tensors as f32). Indices < 50000 < 2^24 are exactly representable.
__global__ void k_out(float* __restrict__ out) {
    int i = blockIdx.x * blockDim.x + threadIdx.x;
    if (i < T_TOTAL) {
        unsigned v = 0xFFFFFFFFu - (unsigned)(g_best[i] & 0xFFFFFFFFull);
        out[i] = (float)v;
    }
}

extern "C" void kernel_launch(void* const* d_in, const int* in_sizes, int n_in,
                              void* d_out, int out_size) {
    // Element-count dispatch (stub: in_sizes[i] IS the element count),
    // positional fallback.
    const float* batch = nullptr;
    const float* emb   = nullptr;
    for (int i = 0; i < n_in; i++) {
        if (in_sizes[i] == BATCH_ELEMS && !batch) batch = (const float*)d_in[i];
        else if (in_sizes[i] == EMB_ELEMS && !emb) emb = (const float*)d_in[i];
    }
    if (!batch) batch = (const float*)d_in[0];
    if (!emb)   emb   = (const float*)d_in[1];
    float* out = (float*)d_out;  // [4096] float32 (hypothesis)

    k_init<<<16, 256>>>();
    k_norm<<<6250, 256>>>(emb);                 // 6250*8 warps = 50000 rows
    dim3 grid((V_TOTAL + TN - 1) / TN, T_TOTAL / TM); // (391, 32)
    k_gemm<<<grid, 256>>>(batch, emb);
    k_out<<<16, 256>>>(out);
}

// round 16
// speedup vs baseline: 1.0299x; 1.0299x over previous
#include <cuda_runtime.h>
#include <math.h>

#define V_TOTAL 50000
#define E_DIM   512
#define T_TOTAL 4096
#define BATCH_ELEMS 2097152    // 8*512*512
#define EMB_ELEMS   25600000   // 50000*512

#define TM 128
#define TN 128
#define BK 32
#define S_STRIDE 132   // padded shared stride (floats)

// Scratch (allocation-free rule: __device__ globals)
__device__ float g_inv_norm[50048];
__device__ unsigned long long g_best[T_TOTAL];

// ---------- packed f32x2 helpers ----------
__device__ __forceinline__ unsigned long long ffma2(unsigned long long a,
                                                    unsigned long long b,
                                                    unsigned long long c) {
    unsigned long long d;
    asm("fma.rn.f32x2 %0, %1, %2, %3;" : "=l"(d) : "l"(a), "l"(b), "l"(c));
    return d;
}
__device__ __forceinline__ unsigned long long pack2(float x) {
    unsigned long long d;
    asm("mov.b64 %0, {%1, %1};" : "=l"(d) : "f"(x));
    return d;
}
__device__ __forceinline__ float2 unpack2(unsigned long long v) {
    float2 r;
    asm("mov.b64 {%0, %1}, %2;" : "=f"(r.x), "=f"(r.y) : "l"(v));
    return r;
}

// ordered-float + inverted-index key: bigger value wins; ties -> smaller index wins
__device__ __forceinline__ unsigned long long enc_key(float f, unsigned v) {
    unsigned u = __float_as_uint(f);
    u = (u & 0x80000000u) ? ~u : (u | 0x80000000u);
    return ((unsigned long long)u << 32) | (unsigned long long)(0xFFFFFFFFu - v);
}

// ---------- kernel: reset best keys ----------
__global__ void k_init() {
    int i = blockIdx.x * blockDim.x + threadIdx.x;
    if (i < T_TOTAL) g_best[i] = 0ULL;
}

// ---------- kernel: per-row 1/||emb_v|| (one warp per row) ----------
__global__ void k_norm(const float* __restrict__ emb) {
    int warp = (blockIdx.x * blockDim.x + threadIdx.x) >> 5;
    int lane = threadIdx.x & 31;
    if (warp >= V_TOTAL) return;
    const float4* row = (const float4*)(emb + (size_t)warp * E_DIM);
    float s = 0.f;
#pragma unroll
    for (int i = 0; i < 4; i++) {
        float4 v = row[lane + i * 32];
        s += v.x * v.x + v.y * v.y + v.z * v.z + v.w * v.w;
    }
#pragma unroll
    for (int o = 16; o; o >>= 1) s += __shfl_xor_sync(0xffffffffu, s, o);
    // Guard: zero norm -> inv 0 (instead of inf), keeps scores finite.
    if (lane == 0) g_inv_norm[warp] = (s > 0.f) ? (1.0f / sqrtf(s)) : 0.f;
}

// ---------- fused GEMM + argmax (packed f32x2 inner loop) ----------
// C[t][v] = sum_k batch[t][k] * emb[v][k]; score = C * inv_norm[v]; argmax over v.
__global__ __launch_bounds__(256) void k_gemm(const float* __restrict__ A,
                                              const float* __restrict__ B) {
    __shared__ float As[BK][S_STRIDE];
    __shared__ float Bs[BK][S_STRIDE];
    __shared__ unsigned long long rowBest[TM];

    const int tid = threadIdx.x;
    const int tx = tid & 15;        // column group
    const int ty = tid >> 4;        // row group
    const int t0 = blockIdx.y * TM; // token tile base (4096/128 = 32, exact)
    const int v0 = blockIdx.x * TN; // vocab tile base (391 tiles, last partial)

    unsigned long long acc[8][4];
#pragma unroll
    for (int i = 0; i < 8; i++)
#pragma unroll
        for (int j = 0; j < 4; j++) acc[i][j] = 0ULL;

    float4 ar[4], br[4];

    // initial prefetch (kt = 0)
#pragma unroll
    for (int i = 0; i < 4; i++) {
        int q = tid + i * 256;
        int row = q >> 3, kq = q & 7;
        ar[i] = *(const float4*)(A + (size_t)(t0 + row) * E_DIM + kq * 4);
        int v = v0 + row;
        br[i] = (v < V_TOTAL)
                    ? *(const float4*)(B + (size_t)v * E_DIM + kq * 4)
                    : make_float4(0.f, 0.f, 0.f, 0.f);
    }

    for (int kt = 0; kt < E_DIM / BK; kt++) {
        __syncthreads();
        // store prefetched tile (transposed: As[k][row])
#pragma unroll
        for (int i = 0; i < 4; i++) {
            int q = tid + i * 256;
            int row = q >> 3, kq = q & 7;
            As[kq * 4 + 0][row] = ar[i].x;
            As[kq * 4 + 1][row] = ar[i].y;
            As[kq * 4 + 2][row] = ar[i].z;
            As[kq * 4 + 3][row] = ar[i].w;
            Bs[kq * 4 + 0][row] = br[i].x;
            Bs[kq * 4 + 1][row] = br[i].y;
            Bs[kq * 4 + 2][row] = br[i].z;
            Bs[kq * 4 + 3][row] = br[i].w;
        }
        __syncthreads();

        // prefetch next tile
        if (kt + 1 < E_DIM / BK) {
            int k0 = (kt + 1) * BK;
#pragma unroll
            for (int i = 0; i < 4; i++) {
                int q = tid + i * 256;
                int row = q >> 3, kq = q & 7;
                ar[i] = *(const float4*)(A + (size_t)(t0 + row) * E_DIM + k0 + kq * 4);
                int v = v0 + row;
                br[i] = (v < V_TOTAL)
                            ? *(const float4*)(B + (size_t)v * E_DIM + k0 + kq * 4)
                            : make_float4(0.f, 0.f, 0.f, 0.f);
            }
        }

        // compute: rows {4ty..4ty+3, 64+4ty..}, cols {4tx..4tx+3, 64+4tx..}
#pragma unroll
        for (int kk = 0; kk < BK; kk++) {
            float4 a0 = *(const float4*)&As[kk][4 * ty];
            float4 a1 = *(const float4*)&As[kk][64 + 4 * ty];
            ulonglong2 b0 = *(const ulonglong2*)&Bs[kk][4 * tx];
            ulonglong2 b1 = *(const ulonglong2*)&Bs[kk][64 + 4 * tx];
            float a[8] = {a0.x, a0.y, a0.z, a0.w, a1.x, a1.y, a1.z, a1.w};
#pragma unroll
            for (int i = 0; i < 8; i++) {
                unsigned long long ai = pack2(a[i]);
                acc[i][0] = ffma2(ai, b0.x, acc[i][0]);
                acc[i][1] = ffma2(ai, b0.y, acc[i][1]);
                acc[i][2] = ffma2(ai, b1.x, acc[i][2]);
                acc[i][3] = ffma2(ai, b1.y, acc[i][3]);
            }
        }
    }

    // ---- epilogue: scale by inv_norm, per-row argmax ----
    float invc[8];
    int colv[8];
#pragma unroll
    for (int j = 0; j < 8; j++) {
        int c = (j < 4) ? (4 * tx + j) : (64 + 4 * tx + (j - 4));
        int v = v0 + c;
        colv[j] = v;
        invc[j] = (v < V_TOTAL) ? g_inv_norm[v] : 0.f;
    }

    unsigned long long key[8];
#pragma unroll
    for (int i = 0; i < 8; i++) {
        unsigned long long best = 0ULL;
#pragma unroll
        for (int j2 = 0; j2 < 4; j2++) {
            float2 c2 = unpack2(acc[i][j2]);
            int j = 2 * j2;
            if (colv[j] < V_TOTAL) {
                float s0 = c2.x * invc[j];
                if (s0 == s0) {
                    unsigned long long k = enc_key(s0, (unsigned)colv[j]);
                    if (k > best) best = k;
                }
            }
            if (colv[j + 1] < V_TOTAL) {
                float s1 = c2.y * invc[j + 1];
                if (s1 == s1) {
                    unsigned long long k = enc_key(s1, (unsigned)colv[j + 1]);
                    if (k > best) best = k;
                }
            }
        }
        key[i] = best;
    }

    __syncthreads();
    if (tid < TM) rowBest[tid] = 0ULL;
    __syncthreads();
#pragma unroll
    for (int i = 0; i < 8; i++) {
        int r = (i < 4) ? (4 * ty + i) : (64 + 4 * ty + (i - 4));
        if (key[i]) atomicMax(&rowBest[r], key[i]);
    }
    __syncthreads();
    if (tid < TM) {
        unsigned long long k = rowBest[tid];
        if (k) atomicMax(&g_best[t0 + tid], k);
    }
}

// ---------- decode: write winning index as FLOAT32 (confirmed contract) ----------
__global__ void k_out(float* __restrict__ out) {
    int i = blockIdx.x * blockDim.x + threadIdx.x;
    if (i < T_TOTAL) {
        unsigned v = 0xFFFFFFFFu - (unsigned)(g_best[i] & 0xFFFFFFFFull);
        out[i] = (float)v;
    }
}

extern "C" void kernel_launch(void* const* d_in, const int* in_sizes, int n_in,
                              void* d_out, int out_size) {
    // Element-count dispatch, positional fallback (confirmed working).
    const float* batch = nullptr;
    const float* emb   = nullptr;
    for (int i = 0; i < n_in; i++) {
        if (in_sizes[i] == BATCH_ELEMS && !batch) batch = (const float*)d_in[i];
        else if (in_sizes[i] == EMB_ELEMS && !emb) emb = (const float*)d_in[i];
    }
    if (!batch) batch = (const float*)d_in[0];
    if (!emb)   emb   = (const float*)d_in[1];
    float* out = (float*)d_out;  // [4096] float32 (confirmed)

    k_init<<<16, 256>>>();
    k_norm<<<6250, 256>>>(emb);                 // 6250*8 warps = 50000 rows
    dim3 grid((V_TOTAL + TN - 1) / TN, T_TOTAL / TM); // (391, 32)
    k_gemm<<<grid, 256>>>(batch, emb);
    k_out<<<16, 256>>>(out);
}